// round 6
// baseline (speedup 1.0000x reference)
#include <cuda_runtime.h>
#include <cstdint>

// TransferNet: B=8192 sequences, T=1024 steps, C=6 channels.
// s_j(t) = a*feats[b,t,j] + (1-a)*ln( sum_i exp( s_i(t-1)*Tn[i][j] ) )
// s(0) = feats[b,0,:], out[b,t,:] = s(t).
//
// 6 lanes/batch (channel j per lane), 5 groups/warp, 4 warps/block ->
// 20 batches/block. shfl for state exchange. In-place 32-step smem tile,
// fully-unrolled coalesced copies. T split into 8 independent 128-step
// chunks (contraction: error factor ~0.2/step, 11 warmup steps -> ~5e-9).
// Slim block (17.2KB smem, <=64 regs) => 8 blocks/SM resident.

constexpr int T_STEPS  = 1024;
constexpr int C        = 6;
constexpr int BPB      = 20;            // 4 warps * 5 groups
constexpr int NTHREADS = 128;
constexpr int TT       = 32;            // time tile
constexpr int CT       = 128;           // steps per chunk
constexpr int NCHUNK   = T_STEPS / CT;  // 8
constexpr int W        = 12;            // warmup steps (incl. seed)
constexpr int ROW      = T_STEPS * C;   // 6144
constexpr int CHUNK    = TT * C;        // 192 floats per (batch, tile)
constexpr int S_STRIDE = 134;           // 134 % 32 == 6 -> conflict-free
constexpr float LOG2E_F = 1.4426950408889634f;
constexpr float LN2_F   = 0.6931471805599453f;

__device__ __forceinline__ float ex2f(float x) {
    float r; asm("ex2.approx.ftz.f32 %0, %1;" : "=f"(r) : "f"(x)); return r;
}
__device__ __forceinline__ float lg2f(float x) {
    float r; asm("lg2.approx.ftz.f32 %0, %1;" : "=f"(r) : "f"(x)); return r;
}

// s <- a*cur + c2*lg2( sum_i exp2( s_i * t2[i] ) ), c2 = (1-a)*ln2
__device__ __forceinline__ float step6(float s, float cur, const float* t2,
                                       int gbase, float a, float c2) {
    const unsigned FULL = 0xffffffffu;
    float v0 = __shfl_sync(FULL, s, gbase + 0);
    float v1 = __shfl_sync(FULL, s, gbase + 1);
    float v2 = __shfl_sync(FULL, s, gbase + 2);
    float v3 = __shfl_sync(FULL, s, gbase + 3);
    float v4 = __shfl_sync(FULL, s, gbase + 4);
    float v5 = __shfl_sync(FULL, s, gbase + 5);
    float e0 = ex2f(v0 * t2[0]);
    float e1 = ex2f(v1 * t2[1]);
    float e2 = ex2f(v2 * t2[2]);
    float e3 = ex2f(v3 * t2[3]);
    float e4 = ex2f(v4 * t2[4]);
    float e5 = ex2f(v5 * t2[5]);
    float acc = ((e0 + e1) + (e2 + e3)) + (e4 + e5);
    return fmaf(a, cur, c2 * lg2f(acc));
}

__global__ __launch_bounds__(NTHREADS, 8)
void transfer_kernel(const float* __restrict__ feats,
                     const float* __restrict__ alpha,
                     const float* __restrict__ trans,
                     float* __restrict__ out, int B)
{
    __shared__ float tile[TT * S_STRIDE];

    const int tid  = threadIdx.x;
    const int warp = tid >> 5;
    const int lane = tid & 31;
    int g = lane / 6; if (g > 4) g = 4;       // lanes 30,31: dummies
    const int j     = lane - (lane / 6) * 6;
    const int gbase = g * 6;
    const int coff  = warp * 32 + lane;

    const int b0 = blockIdx.x * BPB;
    const int t0 = blockIdx.y * CT;
    int nvalid = B - b0; if (nvalid > BPB) nvalid = BPB;

    // a = sigmoid(alpha)
    const float av = alpha[0];
    const float a  = 1.0f / (1.0f + __expf(-av));
    const float c2 = (1.0f - a) * LN2_F;

    // Row-softmax of transitions; column j, pre-scaled by log2(e)
    float t2[6];
    #pragma unroll
    for (int i = 0; i < 6; ++i) {
        float row[6], m = -1e30f;
        #pragma unroll
        for (int k = 0; k < 6; ++k) { row[k] = trans[i * 6 + k]; m = fmaxf(m, row[k]); }
        float sum = 0.f, ej = 0.f;
        #pragma unroll
        for (int k = 0; k < 6; ++k) {
            float e = ex2f((row[k] - m) * LOG2E_F);
            sum += e;
            if (k == j) ej = e;
        }
        t2[i] = (ej / sum) * LOG2E_F;
    }

    // ---- copy mapping for CHUNK=192 = 1.5*128: per 2 batches, 3 rounds.
    //   round 0: (bl+0, r=tid)
    //   round 1: tid<64 -> (bl+0, r=128+tid) ; tid>=64 -> (bl+1, r=tid-64)
    //   round 2: (bl+1, r=64+tid)
    // All offsets constant per thread; each warp accesses const+lane. ----
    const bool lo = (tid < 64);
    const int rA = tid;
    const int rB = lo ? (128 + tid) : (tid - 64);
    const int rC = 64 + tid;
    const int dB = lo ? 0 : 1;                 // bl delta for round 1
    const int sA = (rA / 6) * S_STRIDE + (rA % 6);
    const int sB = (rB / 6) * S_STRIDE + (rB % 6);
    const int sC = (rC / 6) * S_STRIDE + (rC % 6);

    float s = 0.f;

    // ---- warmup for chunks > 0: seed at t0-W, 11 unstored steps.
    //      Inputs consumed in two batches of 6 to keep regs low. ----
    if (blockIdx.y > 0) {
        int bb = b0 + warp * 5 + g; if (bb >= B) bb = B - 1;
        const float* fp = feats + (size_t)bb * ROW + (size_t)(t0 - W) * C + j;
        float cw[6];
        #pragma unroll
        for (int w = 0; w < 6; ++w) cw[w] = fp[w * C];
        s = cw[0];
        #pragma unroll
        for (int w = 1; w < 6; ++w) s = step6(s, cw[w], t2, gbase, a, c2);
        #pragma unroll
        for (int w = 0; w < 6; ++w) cw[w] = fp[(6 + w) * C];
        #pragma unroll
        for (int w = 0; w < 6; ++w) s = step6(s, cw[w], t2, gbase, a, c2);
    }

    for (int tc = 0; tc < CT; tc += TT) {
        const size_t gofs = (size_t)b0 * ROW + (size_t)(t0 + tc) * C;
        const float* gsrc = feats + gofs;

        // ---- phase 1: coalesced load (global -> smem) ----
        #pragma unroll
        for (int bp = 0; bp < BPB / 2; ++bp) {          // pairs of batches
            const int bl = bp * 2;
            const int sb0 = (bl / 5) * 32 + (bl % 5) * 6;         // compile-time
            const int sb1 = ((bl + 1) / 5) * 32 + ((bl + 1) % 5) * 6;
            if (bl + 1 < nvalid) {
                const float* g0 = gsrc + (size_t)bl * ROW;
                tile[sA + sb0] = g0[rA];
                tile[sB + (dB ? sb1 : sb0)] = g0[dB * ROW + rB];
                tile[sC + sb1] = g0[ROW + rC];
            } else if (bl < nvalid) {                    // only bl valid
                const float* g0 = gsrc + (size_t)bl * ROW;
                tile[sA + sb0] = g0[rA];
                if (lo) tile[sB + sb0] = g0[rB];
            }
        }
        __syncthreads();

        // ---- phase 2: recurrence over this tile (in-place) ----
        int tstart = 0;
        if (blockIdx.y == 0 && tc == 0) { s = tile[coff]; tstart = 1; }

        #pragma unroll 4
        for (int tt = tstart; tt < TT; ++tt) {
            float cur = tile[tt * S_STRIDE + coff];
            s = step6(s, cur, t2, gbase, a, c2);
            tile[tt * S_STRIDE + coff] = s;
        }
        __syncthreads();

        // ---- phase 3: coalesced store (smem -> global) ----
        float* gdst = out + gofs;
        #pragma unroll
        for (int bp = 0; bp < BPB / 2; ++bp) {
            const int bl = bp * 2;
            const int sb0 = (bl / 5) * 32 + (bl % 5) * 6;
            const int sb1 = ((bl + 1) / 5) * 32 + ((bl + 1) % 5) * 6;
            if (bl + 1 < nvalid) {
                float* g0 = gdst + (size_t)bl * ROW;
                g0[rA] = tile[sA + sb0];
                g0[dB * ROW + rB] = tile[sB + (dB ? sb1 : sb0)];
                g0[ROW + rC] = tile[sC + sb1];
            } else if (bl < nvalid) {
                float* g0 = gdst + (size_t)bl * ROW;
                g0[rA] = tile[sA + sb0];
                if (lo) g0[rB] = tile[sB + sb0];
            }
        }
        __syncthreads();
    }
}

extern "C" void kernel_launch(void* const* d_in, const int* in_sizes, int n_in,
                              void* d_out, int out_size) {
    const float* feats = (const float*)d_in[0];
    const float* alpha = (const float*)d_in[1];
    const float* trans = (const float*)d_in[2];
    float* out = (float*)d_out;
    (void)n_in; (void)out_size;

    int B = in_sizes[0] / (T_STEPS * C);
    dim3 grid((B + BPB - 1) / BPB, NCHUNK);
    transfer_kernel<<<grid, NTHREADS>>>(feats, alpha, trans, out, B);
}